// round 15
// baseline (speedup 1.0000x reference)
#include <cuda_runtime.h>

#define DIN    9
#define NPAIR  45
#define NTRI   165

// smem basis layout (floats), channel-natural:
//  A:   9 rows * 4  =  36  @ 0     (ch: [e0, e1p0, e1p1, e1p2])
//  B:  45 rows * 12 = 540  @ 36    (ch: [e2s0..2, e3s0p0..s1p2, pad3])
//  C: 165 rows * 12 = 1980 @ 576   (ch: [e4s0..3, e5s0p0..s1p2, pad2])
#define SB_TOTAL 2556

typedef unsigned long long u64;

__device__ __forceinline__ u64 pk2(float lo, float hi) {
    u64 r; asm("mov.b64 %0, {%1, %2};" : "=l"(r) : "f"(lo), "f"(hi)); return r;
}
__device__ __forceinline__ void upk2(float& lo, float& hi, u64 v) {
    asm("mov.b64 {%0, %1}, %2;" : "=f"(lo), "=f"(hi) : "l"(v));
}
__device__ __forceinline__ u64 ffma2(u64 a, u64 b, u64 c) {
    u64 d; asm("fma.rn.f32x2 %0, %1, %2, %3;" : "=l"(d) : "l"(a), "l"(b), "l"(c)); return d;
}
__device__ __forceinline__ u64 fmul2(u64 a, u64 b) {
    u64 d; asm("mul.rn.f32x2 %0, %1, %2;" : "=l"(d) : "l"(a), "l"(b)); return d;
}
__device__ __forceinline__ u64 duplo(u64 v) { float lo, hi; upk2(lo, hi, v); return pk2(lo, lo); }
__device__ __forceinline__ u64 duphi(u64 v) { float lo, hi; upk2(lo, hi, v); return pk2(hi, hi); }

// scheduling fence: forbids LDS hoisting across group boundaries -> bounded
// live ranges -> reg cap holds without spills.
#define SCHED_FENCE() asm volatile("" ::: "memory")

// per-item epilogue: W loads batched first (MLP), then the FMA chain.
__device__ __forceinline__ void epilogue(
    const float* TAs, const float* TBs, const float* TCs,
    const float* __restrict__ W0, const float* __restrict__ W1,
    const float* __restrict__ W2, const float* __restrict__ W3,
    const float* __restrict__ W4, const float* __restrict__ W5,
    int e, int m, float* obase)
{
    const float w0 = W0[e * 128 + m];
    const float w1 = W1[e * 128 + m];
    float w2[3], w3[2], w4[4], w5[2];
    #pragma unroll
    for (int s = 0; s < 3; s++) w2[s] = W2[(e * 3 + s) * 128 + m];
    #pragma unroll
    for (int s = 0; s < 2; s++) w3[s] = W3[(e * 2 + s) * 128 + m];
    #pragma unroll
    for (int s = 0; s < 4; s++) w4[s] = W4[(e * 4 + s) * 128 + m];
    #pragma unroll
    for (int s = 0; s < 2; s++) w5[s] = W5[(e * 2 + s) * 128 + m];

    float o0 = w0 * TAs[0];
    #pragma unroll
    for (int s = 0; s < 3; s++) o0 = fmaf(w2[s], TBs[s], o0);
    #pragma unroll
    for (int s = 0; s < 4; s++) o0 = fmaf(w4[s], TCs[s], o0);

    float o1[3];
    #pragma unroll
    for (int p = 0; p < 3; p++) o1[p] = w1 * TAs[1 + p];
    #pragma unroll
    for (int s = 0; s < 2; s++) {
        #pragma unroll
        for (int p = 0; p < 3; p++) o1[p] = fmaf(w3[s], TBs[3 + s * 3 + p], o1[p]);
    }
    #pragma unroll
    for (int s = 0; s < 2; s++) {
        #pragma unroll
        for (int p = 0; p < 3; p++) o1[p] = fmaf(w5[s], TCs[4 + s * 3 + p], o1[p]);
    }

    obase[m] = o0;
    #pragma unroll
    for (int p = 0; p < 3; p++) obase[128 + m * 3 + p] = o1[p];
}

// ---------------------------------------------------------------------------
// blockDim = (64, 2): 2 nodes per block, 2 items (m, m+64) per thread.
// Reg cap 102 (128 thr x 5 CTAs) held by per-group scheduling fences.
// ---------------------------------------------------------------------------
__global__ void __launch_bounds__(128, 5)
symcon_kernel(const float* __restrict__ feats,   // (N, 1152)
              const int*   __restrict__ species, // (N,)
              const float* __restrict__ b0, const float* __restrict__ b1,
              const float* __restrict__ b2, const float* __restrict__ b3,
              const float* __restrict__ b4, const float* __restrict__ b5,
              const float* __restrict__ W0, const float* __restrict__ W1,
              const float* __restrict__ W2, const float* __restrict__ W3,
              const float* __restrict__ W4, const float* __restrict__ W5,
              float* __restrict__ out)            // (N, 512)
{
    __shared__ float sb[SB_TOTAL];   // 10224 B

    const int tid = threadIdx.y * 64 + threadIdx.x;

    const int m0 = threadIdx.x;          // 0..63
    const int m1 = m0 + 64;
    const int n  = blockIdx.x * 2 + threadIdx.y;

    // ---- hoisted global loads (latency hides behind prep) ----
    const int e = species[n];
    const float* fbase = feats + n * 1152;

    u64 f2[9];
    f2[0] = pk2(fbase[m0], fbase[m1]);
    #pragma unroll
    for (int k = 0; k < 3; k++)
        f2[1 + k] = pk2(fbase[128 + m0 * 3 + k], fbase[128 + m1 * 3 + k]);
    #pragma unroll
    for (int k = 0; k < 5; k++)
        f2[4 + k] = pk2(fbase[512 + m0 * 5 + k], fbase[512 + m1 * 5 + k]);

    // ---- fused prep: symmetrize bases into smem (128 threads) ----
    if (tid < DIN) {
        float* row = sb + tid * 4;
        row[0] = b0[tid];
        #pragma unroll
        for (int p = 0; p < 3; p++) row[1 + p] = b1[tid * 3 + p];
    }
    if (tid < NPAIR) {
        int a = 0, rem = tid;
        while (rem >= DIN - a) { rem -= DIN - a; a++; }
        const int b = a + rem;
        float* row = sb + 36 + tid * 12;
        #pragma unroll
        for (int s = 0; s < 3; s++) {
            float v = b2[(a * 9 + b) * 3 + s];
            if (a != b) v += b2[(b * 9 + a) * 3 + s];
            row[s] = v;
        }
        #pragma unroll
        for (int s = 0; s < 2; s++)
            #pragma unroll
            for (int p = 0; p < 3; p++) {
                float v = b3[((a * 9 + b) * 2 + s) * 3 + p];
                if (a != b) v += b3[((b * 9 + a) * 2 + s) * 3 + p];
                row[3 + s * 3 + p] = v;
            }
        row[9] = 0.f; row[10] = 0.f; row[11] = 0.f;
    }
    for (int t = tid; t < NTRI; t += 128) {
        // decode triple index -> (a, b, c), a <= b <= c
        int a = 0, rem = t;
        for (;; a++) {
            const int cnt = (DIN - a) * (DIN - a + 1) / 2;
            if (rem < cnt) break;
            rem -= cnt;
        }
        int b = a;
        for (;; b++) {
            const int cnt = DIN - b;
            if (rem < cnt) break;
            rem -= cnt;
        }
        const int c = b + rem;

        const int pi[6] = {a, a, b, b, c, c};
        const int pj[6] = {b, c, a, c, a, b};
        const int pk[6] = {c, b, c, a, b, a};
        float acc[10];
        #pragma unroll
        for (int q = 0; q < 10; q++) acc[q] = 0.f;
        for (int q = 0; q < 6; q++) {
            bool dup = false;
            for (int r = 0; r < q; r++)
                if (pi[r] == pi[q] && pj[r] == pj[q] && pk[r] == pk[q]) { dup = true; break; }
            if (dup) continue;
            const int base = (pi[q] * 9 + pj[q]) * 9 + pk[q];
            for (int s = 0; s < 4; s++) acc[s] += b4[base * 4 + s];
            for (int s = 0; s < 2; s++)
                for (int p = 0; p < 3; p++)
                    acc[4 + s * 3 + p] += b5[(base * 2 + s) * 3 + p];
        }
        float* row = sb + 576 + t * 12;
        #pragma unroll
        for (int q = 0; q < 10; q++) row[q] = acc[q];
        row[10] = 0.f; row[11] = 0.f;
    }
    __syncthreads();

    // smem views (u64 units; A row a at a*2, B row pr at 18+pr*6, C row t3 at 288+t3*6)
    const u64* sbu = reinterpret_cast<const u64*>(sb);

    // channel-pair accumulators, separate per item
    u64 A0[2], A1[2], B0[5], B1[5], C0[5], C1[5];
    #pragma unroll
    for (int q = 0; q < 2; q++) { A0[q] = 0ull; A1[q] = 0ull; }
    #pragma unroll
    for (int q = 0; q < 5; q++) { B0[q] = 0ull; B1[q] = 0ull; C0[q] = 0ull; C1[q] = 0ull; }

    // nu=2 + nu=3 fused, with a scheduling fence per (a,b) group
    {
        int pr = 0, t3 = 0;
        #pragma unroll
        for (int a = 0; a < 9; a++) {
            #pragma unroll
            for (int b = a; b < 9; b++) {
                const u64 Pab = fmul2(f2[a], f2[b]);
                const u64 dp0 = duplo(Pab);
                const u64 dp1 = duphi(Pab);
                {
                    const u64* r = sbu + 18 + pr * 6;
                    const ulonglong2 v01 = *reinterpret_cast<const ulonglong2*>(r);
                    const ulonglong2 v23 = *reinterpret_cast<const ulonglong2*>(r + 2);
                    const u64 v4 = r[4];
                    B0[0] = ffma2(v01.x, dp0, B0[0]);
                    B0[1] = ffma2(v01.y, dp0, B0[1]);
                    B0[2] = ffma2(v23.x, dp0, B0[2]);
                    B0[3] = ffma2(v23.y, dp0, B0[3]);
                    B0[4] = ffma2(v4,    dp0, B0[4]);
                    B1[0] = ffma2(v01.x, dp1, B1[0]);
                    B1[1] = ffma2(v01.y, dp1, B1[1]);
                    B1[2] = ffma2(v23.x, dp1, B1[2]);
                    B1[3] = ffma2(v23.y, dp1, B1[3]);
                    B1[4] = ffma2(v4,    dp1, B1[4]);
                }
                #pragma unroll
                for (int c = b; c < 9; c++) {
                    const u64 Fv = fmul2(Pab, f2[c]);
                    const u64 d0 = duplo(Fv);
                    const u64 d1 = duphi(Fv);
                    const u64* r = sbu + 288 + t3 * 6;
                    const ulonglong2 w01 = *reinterpret_cast<const ulonglong2*>(r);
                    const ulonglong2 w23 = *reinterpret_cast<const ulonglong2*>(r + 2);
                    const u64 w4 = r[4];
                    C0[0] = ffma2(w01.x, d0, C0[0]);
                    C0[1] = ffma2(w01.y, d0, C0[1]);
                    C0[2] = ffma2(w23.x, d0, C0[2]);
                    C0[3] = ffma2(w23.y, d0, C0[3]);
                    C0[4] = ffma2(w4,    d0, C0[4]);
                    C1[0] = ffma2(w01.x, d1, C1[0]);
                    C1[1] = ffma2(w01.y, d1, C1[1]);
                    C1[2] = ffma2(w23.x, d1, C1[2]);
                    C1[3] = ffma2(w23.y, d1, C1[3]);
                    C1[4] = ffma2(w4,    d1, C1[4]);
                    t3++;
                }
                pr++;
                SCHED_FENCE();   // bound live ranges: no LDS hoisting past here
            }
        }
    }

    // nu=1 last: short dup chains overlap the epilogue window
    #pragma unroll
    for (int a = 0; a < 9; a++) {
        const ulonglong2 v = *reinterpret_cast<const ulonglong2*>(sbu + a * 2);
        const u64 d0 = duplo(f2[a]);
        const u64 d1 = duphi(f2[a]);
        A0[0] = ffma2(v.x, d0, A0[0]);
        A0[1] = ffma2(v.y, d0, A0[1]);
        A1[0] = ffma2(v.x, d1, A1[0]);
        A1[1] = ffma2(v.y, d1, A1[1]);
    }

    // unpack accumulators and run per-item epilogue
    float* obase = out + n * 512;
    {
        float TAs[4], TBs[10], TCs[10];
        upk2(TAs[0], TAs[1], A0[0]); upk2(TAs[2], TAs[3], A0[1]);
        #pragma unroll
        for (int q = 0; q < 5; q++) upk2(TBs[2 * q], TBs[2 * q + 1], B0[q]);
        #pragma unroll
        for (int q = 0; q < 5; q++) upk2(TCs[2 * q], TCs[2 * q + 1], C0[q]);
        epilogue(TAs, TBs, TCs, W0, W1, W2, W3, W4, W5, e, m0, obase);
    }
    {
        float TAs[4], TBs[10], TCs[10];
        upk2(TAs[0], TAs[1], A1[0]); upk2(TAs[2], TAs[3], A1[1]);
        #pragma unroll
        for (int q = 0; q < 5; q++) upk2(TBs[2 * q], TBs[2 * q + 1], B1[q]);
        #pragma unroll
        for (int q = 0; q < 5; q++) upk2(TCs[2 * q], TCs[2 * q + 1], C1[q]);
        epilogue(TAs, TBs, TCs, W0, W1, W2, W3, W4, W5, e, m1, obase);
    }
}

// ---------------------------------------------------------------------------
extern "C" void kernel_launch(void* const* d_in, const int* in_sizes, int n_in,
                              void* d_out, int out_size)
{
    const float* feats   = (const float*)d_in[0];
    const int*   species = (const int*)  d_in[1];
    const float* b0 = (const float*)d_in[2];
    const float* w0 = (const float*)d_in[3];
    const float* b1 = (const float*)d_in[4];
    const float* w1 = (const float*)d_in[5];
    const float* b2 = (const float*)d_in[6];
    const float* w2 = (const float*)d_in[7];
    const float* b3 = (const float*)d_in[8];
    const float* w3 = (const float*)d_in[9];
    const float* b4 = (const float*)d_in[10];
    const float* w4 = (const float*)d_in[11];
    const float* b5 = (const float*)d_in[12];
    const float* w5 = (const float*)d_in[13];
    float* out = (float*)d_out;

    dim3 block(64, 2);
    dim3 grid(2048 / 2);
    symcon_kernel<<<grid, block>>>(feats, species,
                                   b0, b1, b2, b3, b4, b5,
                                   w0, w1, w2, w3, w4, w5, out);
}

// round 16
// speedup vs baseline: 1.0559x; 1.0559x over previous
#include <cuda_runtime.h>

#define DIN    9
#define NPAIR  45
#define NTRI   165

// smem basis layout (floats), channel-natural:
//  A:   9 rows * 4  =  36  @ 0     (ch: [e0, e1p0, e1p1, e1p2])
//  B:  45 rows * 12 = 540  @ 36    (ch: [e2s0..2, e3s0p0..s1p2, pad3])
//  C: 165 rows * 12 = 1980 @ 576   (ch: [e4s0..3, e5s0p0..s1p2, pad2])
#define SB_TOTAL 2556

typedef unsigned long long u64;

__device__ __forceinline__ u64 pk2(float lo, float hi) {
    u64 r; asm("mov.b64 %0, {%1, %2};" : "=l"(r) : "f"(lo), "f"(hi)); return r;
}
__device__ __forceinline__ void upk2(float& lo, float& hi, u64 v) {
    asm("mov.b64 {%0, %1}, %2;" : "=f"(lo), "=f"(hi) : "l"(v));
}
__device__ __forceinline__ u64 ffma2(u64 a, u64 b, u64 c) {
    u64 d; asm("fma.rn.f32x2 %0, %1, %2, %3;" : "=l"(d) : "l"(a), "l"(b), "l"(c)); return d;
}
__device__ __forceinline__ u64 fmul2(u64 a, u64 b) {
    u64 d; asm("mul.rn.f32x2 %0, %1, %2;" : "=l"(d) : "l"(a), "l"(b)); return d;
}
__device__ __forceinline__ u64 duplo(u64 v) { float lo, hi; upk2(lo, hi, v); return pk2(lo, lo); }
__device__ __forceinline__ u64 duphi(u64 v) { float lo, hi; upk2(lo, hi, v); return pk2(hi, hi); }

// per-item epilogue: scalar weight contraction + store (champion order)
__device__ __forceinline__ void epilogue(
    const float* TAs, const float* TBs, const float* TCs,
    const float* __restrict__ W0, const float* __restrict__ W1,
    const float* __restrict__ W2, const float* __restrict__ W3,
    const float* __restrict__ W4, const float* __restrict__ W5,
    int e, int m, float* obase)
{
    float o0 = W0[e * 128 + m] * TAs[0];
    #pragma unroll
    for (int s = 0; s < 3; s++) o0 = fmaf(W2[(e * 3 + s) * 128 + m], TBs[s], o0);
    #pragma unroll
    for (int s = 0; s < 4; s++) o0 = fmaf(W4[(e * 4 + s) * 128 + m], TCs[s], o0);

    float o1[3];
    const float w1 = W1[e * 128 + m];
    #pragma unroll
    for (int p = 0; p < 3; p++) o1[p] = w1 * TAs[1 + p];
    #pragma unroll
    for (int s = 0; s < 2; s++) {
        const float w = W3[(e * 2 + s) * 128 + m];
        #pragma unroll
        for (int p = 0; p < 3; p++) o1[p] = fmaf(w, TBs[3 + s * 3 + p], o1[p]);
    }
    #pragma unroll
    for (int s = 0; s < 2; s++) {
        const float w = W5[(e * 2 + s) * 128 + m];
        #pragma unroll
        for (int p = 0; p < 3; p++) o1[p] = fmaf(w, TCs[4 + s * 3 + p], o1[p]);
    }

    obase[m] = o0;
    #pragma unroll
    for (int p = 0; p < 3; p++) obase[128 + m * 3 + p] = o1[p];
}

// ---------------------------------------------------------------------------
// blockDim = (64, 4): 4 nodes per block, 2 items (m, m+64) per thread.
// Champion (round-3) formulation; prep symmetrization uses a closed-form
// multiplicity factor instead of permutation-dedup loops.
// ---------------------------------------------------------------------------
__global__ void __launch_bounds__(256, 2)
symcon_kernel(const float* __restrict__ feats,   // (N, 1152)
              const int*   __restrict__ species, // (N,)
              const float* __restrict__ b0, const float* __restrict__ b1,
              const float* __restrict__ b2, const float* __restrict__ b3,
              const float* __restrict__ b4, const float* __restrict__ b5,
              const float* __restrict__ W0, const float* __restrict__ W1,
              const float* __restrict__ W2, const float* __restrict__ W3,
              const float* __restrict__ W4, const float* __restrict__ W5,
              float* __restrict__ out)            // (N, 512)
{
    __shared__ float sb[SB_TOTAL];   // 10224 B

    const int tid = threadIdx.y * 64 + threadIdx.x;

    const int m0 = threadIdx.x;          // 0..63
    const int m1 = m0 + 64;
    const int n  = blockIdx.x * 4 + threadIdx.y;

    // ---- hoisted global loads (latency hides behind prep) ----
    const int e = species[n];
    const float* fbase = feats + n * 1152;

    u64 f2[9];
    f2[0] = pk2(fbase[m0], fbase[m1]);
    #pragma unroll
    for (int k = 0; k < 3; k++)
        f2[1 + k] = pk2(fbase[128 + m0 * 3 + k], fbase[128 + m1 * 3 + k]);
    #pragma unroll
    for (int k = 0; k < 5; k++)
        f2[4 + k] = pk2(fbase[512 + m0 * 5 + k], fbase[512 + m1 * 5 + k]);

    // ---- fused prep: symmetrize bases into smem ----
    if (tid < DIN) {
        float* row = sb + tid * 4;
        row[0] = b0[tid];
        #pragma unroll
        for (int p = 0; p < 3; p++) row[1 + p] = b1[tid * 3 + p];
    }
    if (tid < NPAIR) {
        int a = 0, rem = tid;
        while (rem >= DIN - a) { rem -= DIN - a; a++; }
        const int b = a + rem;
        float* row = sb + 36 + tid * 12;
        #pragma unroll
        for (int s = 0; s < 3; s++) {
            float v = b2[(a * 9 + b) * 3 + s];
            if (a != b) v += b2[(b * 9 + a) * 3 + s];
            row[s] = v;
        }
        #pragma unroll
        for (int s = 0; s < 2; s++)
            #pragma unroll
            for (int p = 0; p < 3; p++) {
                float v = b3[((a * 9 + b) * 2 + s) * 3 + p];
                if (a != b) v += b3[((b * 9 + a) * 2 + s) * 3 + p];
                row[3 + s * 3 + p] = v;
            }
        row[9] = 0.f; row[10] = 0.f; row[11] = 0.f;
    }
    if (tid < NTRI) {
        // decode triple index -> (a, b, c), a <= b <= c
        int a = 0, rem = tid;
        for (;; a++) {
            const int cnt = (DIN - a) * (DIN - a + 1) / 2;
            if (rem < cnt) break;
            rem -= cnt;
        }
        int b = a;
        for (;; b++) {
            const int cnt = DIN - b;
            if (rem < cnt) break;
            rem -= cnt;
        }
        const int c = b + rem;

        // sum over ALL 6 permutations, then scale by distinct/6:
        //   all distinct -> 1, one pair equal -> 1/2, all equal -> 1/6
        const int pi[6] = {a, a, b, b, c, c};
        const int pj[6] = {b, c, a, c, a, b};
        const int pk[6] = {c, b, c, a, b, a};
        float acc[10];
        #pragma unroll
        for (int q = 0; q < 10; q++) acc[q] = 0.f;
        #pragma unroll
        for (int q = 0; q < 6; q++) {
            const int base = (pi[q] * 9 + pj[q]) * 9 + pk[q];
            #pragma unroll
            for (int s = 0; s < 4; s++) acc[s] += b4[base * 4 + s];
            #pragma unroll
            for (int s = 0; s < 2; s++)
                #pragma unroll
                for (int p = 0; p < 3; p++)
                    acc[4 + s * 3 + p] += b5[(base * 2 + s) * 3 + p];
        }
        const float scale = (a == b) ? ((b == c) ? (1.f / 6.f) : 0.5f)
                                     : ((b == c) ? 0.5f : 1.f);
        float* row = sb + 576 + tid * 12;
        #pragma unroll
        for (int q = 0; q < 10; q++) row[q] = acc[q] * scale;
        row[10] = 0.f; row[11] = 0.f;
    }
    __syncthreads();

    // smem views (u64 units; A row a at a*2, B row pr at 18+pr*6, C row t3 at 288+t3*6)
    const u64* sbu = reinterpret_cast<const u64*>(sb);

    // channel-pair accumulators, separate per item
    u64 A0[2], A1[2], B0[5], B1[5], C0[5], C1[5];
    #pragma unroll
    for (int q = 0; q < 2; q++) { A0[q] = 0ull; A1[q] = 0ull; }
    #pragma unroll
    for (int q = 0; q < 5; q++) { B0[q] = 0ull; B1[q] = 0ull; C0[q] = 0ull; C1[q] = 0ull; }

    // nu=1
    #pragma unroll
    for (int a = 0; a < 9; a++) {
        const ulonglong2 v = *reinterpret_cast<const ulonglong2*>(sbu + a * 2);
        const u64 d0 = duplo(f2[a]);
        const u64 d1 = duphi(f2[a]);
        A0[0] = ffma2(v.x, d0, A0[0]);
        A0[1] = ffma2(v.y, d0, A0[1]);
        A1[0] = ffma2(v.x, d1, A1[0]);
        A1[1] = ffma2(v.y, d1, A1[1]);
    }

    // nu=2 + nu=3 fused
    {
        int pr = 0, t3 = 0;
        #pragma unroll
        for (int a = 0; a < 9; a++) {
            #pragma unroll
            for (int b = a; b < 9; b++) {
                const u64 Pab = fmul2(f2[a], f2[b]);
                const u64 dp0 = duplo(Pab);
                const u64 dp1 = duphi(Pab);
                {
                    const u64* r = sbu + 18 + pr * 6;
                    const ulonglong2 v01 = *reinterpret_cast<const ulonglong2*>(r);
                    const ulonglong2 v23 = *reinterpret_cast<const ulonglong2*>(r + 2);
                    const u64 v4 = r[4];
                    B0[0] = ffma2(v01.x, dp0, B0[0]);
                    B0[1] = ffma2(v01.y, dp0, B0[1]);
                    B0[2] = ffma2(v23.x, dp0, B0[2]);
                    B0[3] = ffma2(v23.y, dp0, B0[3]);
                    B0[4] = ffma2(v4,    dp0, B0[4]);
                    B1[0] = ffma2(v01.x, dp1, B1[0]);
                    B1[1] = ffma2(v01.y, dp1, B1[1]);
                    B1[2] = ffma2(v23.x, dp1, B1[2]);
                    B1[3] = ffma2(v23.y, dp1, B1[3]);
                    B1[4] = ffma2(v4,    dp1, B1[4]);
                }
                #pragma unroll
                for (int c = b; c < 9; c++) {
                    const u64 Fv = fmul2(Pab, f2[c]);
                    const u64 d0 = duplo(Fv);
                    const u64 d1 = duphi(Fv);
                    const u64* r = sbu + 288 + t3 * 6;
                    const ulonglong2 w01 = *reinterpret_cast<const ulonglong2*>(r);
                    const ulonglong2 w23 = *reinterpret_cast<const ulonglong2*>(r + 2);
                    const u64 w4 = r[4];
                    C0[0] = ffma2(w01.x, d0, C0[0]);
                    C0[1] = ffma2(w01.y, d0, C0[1]);
                    C0[2] = ffma2(w23.x, d0, C0[2]);
                    C0[3] = ffma2(w23.y, d0, C0[3]);
                    C0[4] = ffma2(w4,    d0, C0[4]);
                    C1[0] = ffma2(w01.x, d1, C1[0]);
                    C1[1] = ffma2(w01.y, d1, C1[1]);
                    C1[2] = ffma2(w23.x, d1, C1[2]);
                    C1[3] = ffma2(w23.y, d1, C1[3]);
                    C1[4] = ffma2(w4,    d1, C1[4]);
                    t3++;
                }
                pr++;
            }
        }
    }

    // unpack accumulators and run per-item epilogue
    float* obase = out + n * 512;
    {
        float TAs[4], TBs[10], TCs[10];
        upk2(TAs[0], TAs[1], A0[0]); upk2(TAs[2], TAs[3], A0[1]);
        #pragma unroll
        for (int q = 0; q < 5; q++) upk2(TBs[2 * q], TBs[2 * q + 1], B0[q]);
        #pragma unroll
        for (int q = 0; q < 5; q++) upk2(TCs[2 * q], TCs[2 * q + 1], C0[q]);
        epilogue(TAs, TBs, TCs, W0, W1, W2, W3, W4, W5, e, m0, obase);
    }
    {
        float TAs[4], TBs[10], TCs[10];
        upk2(TAs[0], TAs[1], A1[0]); upk2(TAs[2], TAs[3], A1[1]);
        #pragma unroll
        for (int q = 0; q < 5; q++) upk2(TBs[2 * q], TBs[2 * q + 1], B1[q]);
        #pragma unroll
        for (int q = 0; q < 5; q++) upk2(TCs[2 * q], TCs[2 * q + 1], C1[q]);
        epilogue(TAs, TBs, TCs, W0, W1, W2, W3, W4, W5, e, m1, obase);
    }
}

// ---------------------------------------------------------------------------
extern "C" void kernel_launch(void* const* d_in, const int* in_sizes, int n_in,
                              void* d_out, int out_size)
{
    const float* feats   = (const float*)d_in[0];
    const int*   species = (const int*)  d_in[1];
    const float* b0 = (const float*)d_in[2];
    const float* w0 = (const float*)d_in[3];
    const float* b1 = (const float*)d_in[4];
    const float* w1 = (const float*)d_in[5];
    const float* b2 = (const float*)d_in[6];
    const float* w2 = (const float*)d_in[7];
    const float* b3 = (const float*)d_in[8];
    const float* w3 = (const float*)d_in[9];
    const float* b4 = (const float*)d_in[10];
    const float* w4 = (const float*)d_in[11];
    const float* b5 = (const float*)d_in[12];
    const float* w5 = (const float*)d_in[13];
    float* out = (float*)d_out;

    dim3 block(64, 4);
    dim3 grid(2048 / 4);
    symcon_kernel<<<grid, block>>>(feats, species,
                                   b0, b1, b2, b3, b4, b5,
                                   w0, w1, w2, w3, w4, w5, out);
}

// round 17
// speedup vs baseline: 1.0645x; 1.0082x over previous
#include <cuda_runtime.h>

#define DIN    9
#define NPAIR  45
#define NTRI   165

// smem basis layout (floats), channel-natural:
//  A:   9 rows * 4  =  36  @ 0     (ch: [e0, e1p0, e1p1, e1p2])
//  B:  45 rows * 12 = 540  @ 36    (ch: [e2s0..2, e3s0p0..s1p2, pad3])
//  C: 165 rows * 12 = 1980 @ 576   (ch: [e4s0..3, e5s0p0..s1p2, pad2])
#define SB_TOTAL 2556

typedef unsigned long long u64;

__device__ __forceinline__ u64 pk2(float lo, float hi) {
    u64 r; asm("mov.b64 %0, {%1, %2};" : "=l"(r) : "f"(lo), "f"(hi)); return r;
}
__device__ __forceinline__ void upk2(float& lo, float& hi, u64 v) {
    asm("mov.b64 {%0, %1}, %2;" : "=f"(lo), "=f"(hi) : "l"(v));
}
__device__ __forceinline__ u64 ffma2(u64 a, u64 b, u64 c) {
    u64 d; asm("fma.rn.f32x2 %0, %1, %2, %3;" : "=l"(d) : "l"(a), "l"(b), "l"(c)); return d;
}
__device__ __forceinline__ u64 fmul2(u64 a, u64 b) {
    u64 d; asm("mul.rn.f32x2 %0, %1, %2;" : "=l"(d) : "l"(a), "l"(b)); return d;
}
__device__ __forceinline__ u64 duplo(u64 v) { float lo, hi; upk2(lo, hi, v); return pk2(lo, lo); }
__device__ __forceinline__ u64 duphi(u64 v) { float lo, hi; upk2(lo, hi, v); return pk2(hi, hi); }

// per-item epilogue: scalar weight contraction + store (champion order)
__device__ __forceinline__ void epilogue(
    const float* TAs, const float* TBs, const float* TCs,
    const float* __restrict__ W0, const float* __restrict__ W1,
    const float* __restrict__ W2, const float* __restrict__ W3,
    const float* __restrict__ W4, const float* __restrict__ W5,
    int e, int m, float* obase)
{
    float o0 = W0[e * 128 + m] * TAs[0];
    #pragma unroll
    for (int s = 0; s < 3; s++) o0 = fmaf(W2[(e * 3 + s) * 128 + m], TBs[s], o0);
    #pragma unroll
    for (int s = 0; s < 4; s++) o0 = fmaf(W4[(e * 4 + s) * 128 + m], TCs[s], o0);

    float o1[3];
    const float w1 = W1[e * 128 + m];
    #pragma unroll
    for (int p = 0; p < 3; p++) o1[p] = w1 * TAs[1 + p];
    #pragma unroll
    for (int s = 0; s < 2; s++) {
        const float w = W3[(e * 2 + s) * 128 + m];
        #pragma unroll
        for (int p = 0; p < 3; p++) o1[p] = fmaf(w, TBs[3 + s * 3 + p], o1[p]);
    }
    #pragma unroll
    for (int s = 0; s < 2; s++) {
        const float w = W5[(e * 2 + s) * 128 + m];
        #pragma unroll
        for (int p = 0; p < 3; p++) o1[p] = fmaf(w, TCs[4 + s * 3 + p], o1[p]);
    }

    obase[m] = o0;
    #pragma unroll
    for (int p = 0; p < 3; p++) obase[128 + m * 3 + p] = o1[p];
}

// ---------------------------------------------------------------------------
// blockDim = (64, 8): 8 nodes per block, 2 items (m, m+64) per thread.
// Identical mainloop/epilogue to the round-16 champion; prep amortized over
// 8 nodes (half the chip-wide prep executions). 512 thr x 128 regs = 1 CTA/SM
// = same 16 warps/SM as the champion.
// ---------------------------------------------------------------------------
__global__ void __launch_bounds__(512, 1)
symcon_kernel(const float* __restrict__ feats,   // (N, 1152)
              const int*   __restrict__ species, // (N,)
              const float* __restrict__ b0, const float* __restrict__ b1,
              const float* __restrict__ b2, const float* __restrict__ b3,
              const float* __restrict__ b4, const float* __restrict__ b5,
              const float* __restrict__ W0, const float* __restrict__ W1,
              const float* __restrict__ W2, const float* __restrict__ W3,
              const float* __restrict__ W4, const float* __restrict__ W5,
              float* __restrict__ out)            // (N, 512)
{
    __shared__ float sb[SB_TOTAL];   // 10224 B

    const int tid = threadIdx.y * 64 + threadIdx.x;

    const int m0 = threadIdx.x;          // 0..63
    const int m1 = m0 + 64;
    const int n  = blockIdx.x * 8 + threadIdx.y;

    // ---- hoisted global loads (latency hides behind prep) ----
    const int e = species[n];
    const float* fbase = feats + n * 1152;

    u64 f2[9];
    f2[0] = pk2(fbase[m0], fbase[m1]);
    #pragma unroll
    for (int k = 0; k < 3; k++)
        f2[1 + k] = pk2(fbase[128 + m0 * 3 + k], fbase[128 + m1 * 3 + k]);
    #pragma unroll
    for (int k = 0; k < 5; k++)
        f2[4 + k] = pk2(fbase[512 + m0 * 5 + k], fbase[512 + m1 * 5 + k]);

    // ---- fused prep: symmetrize bases into smem (one per block of 8 nodes) ----
    if (tid < DIN) {
        float* row = sb + tid * 4;
        row[0] = b0[tid];
        #pragma unroll
        for (int p = 0; p < 3; p++) row[1 + p] = b1[tid * 3 + p];
    }
    if (tid < NPAIR) {
        int a = 0, rem = tid;
        while (rem >= DIN - a) { rem -= DIN - a; a++; }
        const int b = a + rem;
        float* row = sb + 36 + tid * 12;
        #pragma unroll
        for (int s = 0; s < 3; s++) {
            float v = b2[(a * 9 + b) * 3 + s];
            if (a != b) v += b2[(b * 9 + a) * 3 + s];
            row[s] = v;
        }
        #pragma unroll
        for (int s = 0; s < 2; s++)
            #pragma unroll
            for (int p = 0; p < 3; p++) {
                float v = b3[((a * 9 + b) * 2 + s) * 3 + p];
                if (a != b) v += b3[((b * 9 + a) * 2 + s) * 3 + p];
                row[3 + s * 3 + p] = v;
            }
        row[9] = 0.f; row[10] = 0.f; row[11] = 0.f;
    }
    if (tid >= 256 && tid < 256 + NTRI) {
        const int t = tid - 256;
        // decode triple index -> (a, b, c), a <= b <= c
        int a = 0, rem = t;
        for (;; a++) {
            const int cnt = (DIN - a) * (DIN - a + 1) / 2;
            if (rem < cnt) break;
            rem -= cnt;
        }
        int b = a;
        for (;; b++) {
            const int cnt = DIN - b;
            if (rem < cnt) break;
            rem -= cnt;
        }
        const int c = b + rem;

        // sum over ALL 6 permutations, then scale by distinct/6
        const int pi[6] = {a, a, b, b, c, c};
        const int pj[6] = {b, c, a, c, a, b};
        const int pk[6] = {c, b, c, a, b, a};
        float acc[10];
        #pragma unroll
        for (int q = 0; q < 10; q++) acc[q] = 0.f;
        #pragma unroll
        for (int q = 0; q < 6; q++) {
            const int base = (pi[q] * 9 + pj[q]) * 9 + pk[q];
            #pragma unroll
            for (int s = 0; s < 4; s++) acc[s] += b4[base * 4 + s];
            #pragma unroll
            for (int s = 0; s < 2; s++)
                #pragma unroll
                for (int p = 0; p < 3; p++)
                    acc[4 + s * 3 + p] += b5[(base * 2 + s) * 3 + p];
        }
        const float scale = (a == b) ? ((b == c) ? (1.f / 6.f) : 0.5f)
                                     : ((b == c) ? 0.5f : 1.f);
        float* row = sb + 576 + t * 12;
        #pragma unroll
        for (int q = 0; q < 10; q++) row[q] = acc[q] * scale;
        row[10] = 0.f; row[11] = 0.f;
    }
    __syncthreads();

    // smem views (u64 units; A row a at a*2, B row pr at 18+pr*6, C row t3 at 288+t3*6)
    const u64* sbu = reinterpret_cast<const u64*>(sb);

    // channel-pair accumulators, separate per item
    u64 A0[2], A1[2], B0[5], B1[5], C0[5], C1[5];
    #pragma unroll
    for (int q = 0; q < 2; q++) { A0[q] = 0ull; A1[q] = 0ull; }
    #pragma unroll
    for (int q = 0; q < 5; q++) { B0[q] = 0ull; B1[q] = 0ull; C0[q] = 0ull; C1[q] = 0ull; }

    // nu=1
    #pragma unroll
    for (int a = 0; a < 9; a++) {
        const ulonglong2 v = *reinterpret_cast<const ulonglong2*>(sbu + a * 2);
        const u64 d0 = duplo(f2[a]);
        const u64 d1 = duphi(f2[a]);
        A0[0] = ffma2(v.x, d0, A0[0]);
        A0[1] = ffma2(v.y, d0, A0[1]);
        A1[0] = ffma2(v.x, d1, A1[0]);
        A1[1] = ffma2(v.y, d1, A1[1]);
    }

    // nu=2 + nu=3 fused
    {
        int pr = 0, t3 = 0;
        #pragma unroll
        for (int a = 0; a < 9; a++) {
            #pragma unroll
            for (int b = a; b < 9; b++) {
                const u64 Pab = fmul2(f2[a], f2[b]);
                const u64 dp0 = duplo(Pab);
                const u64 dp1 = duphi(Pab);
                {
                    const u64* r = sbu + 18 + pr * 6;
                    const ulonglong2 v01 = *reinterpret_cast<const ulonglong2*>(r);
                    const ulonglong2 v23 = *reinterpret_cast<const ulonglong2*>(r + 2);
                    const u64 v4 = r[4];
                    B0[0] = ffma2(v01.x, dp0, B0[0]);
                    B0[1] = ffma2(v01.y, dp0, B0[1]);
                    B0[2] = ffma2(v23.x, dp0, B0[2]);
                    B0[3] = ffma2(v23.y, dp0, B0[3]);
                    B0[4] = ffma2(v4,    dp0, B0[4]);
                    B1[0] = ffma2(v01.x, dp1, B1[0]);
                    B1[1] = ffma2(v01.y, dp1, B1[1]);
                    B1[2] = ffma2(v23.x, dp1, B1[2]);
                    B1[3] = ffma2(v23.y, dp1, B1[3]);
                    B1[4] = ffma2(v4,    dp1, B1[4]);
                }
                #pragma unroll
                for (int c = b; c < 9; c++) {
                    const u64 Fv = fmul2(Pab, f2[c]);
                    const u64 d0 = duplo(Fv);
                    const u64 d1 = duphi(Fv);
                    const u64* r = sbu + 288 + t3 * 6;
                    const ulonglong2 w01 = *reinterpret_cast<const ulonglong2*>(r);
                    const ulonglong2 w23 = *reinterpret_cast<const ulonglong2*>(r + 2);
                    const u64 w4 = r[4];
                    C0[0] = ffma2(w01.x, d0, C0[0]);
                    C0[1] = ffma2(w01.y, d0, C0[1]);
                    C0[2] = ffma2(w23.x, d0, C0[2]);
                    C0[3] = ffma2(w23.y, d0, C0[3]);
                    C0[4] = ffma2(w4,    d0, C0[4]);
                    C1[0] = ffma2(w01.x, d1, C1[0]);
                    C1[1] = ffma2(w01.y, d1, C1[1]);
                    C1[2] = ffma2(w23.x, d1, C1[2]);
                    C1[3] = ffma2(w23.y, d1, C1[3]);
                    C1[4] = ffma2(w4,    d1, C1[4]);
                    t3++;
                }
                pr++;
            }
        }
    }

    // unpack accumulators and run per-item epilogue
    float* obase = out + n * 512;
    {
        float TAs[4], TBs[10], TCs[10];
        upk2(TAs[0], TAs[1], A0[0]); upk2(TAs[2], TAs[3], A0[1]);
        #pragma unroll
        for (int q = 0; q < 5; q++) upk2(TBs[2 * q], TBs[2 * q + 1], B0[q]);
        #pragma unroll
        for (int q = 0; q < 5; q++) upk2(TCs[2 * q], TCs[2 * q + 1], C0[q]);
        epilogue(TAs, TBs, TCs, W0, W1, W2, W3, W4, W5, e, m0, obase);
    }
    {
        float TAs[4], TBs[10], TCs[10];
        upk2(TAs[0], TAs[1], A1[0]); upk2(TAs[2], TAs[3], A1[1]);
        #pragma unroll
        for (int q = 0; q < 5; q++) upk2(TBs[2 * q], TBs[2 * q + 1], B1[q]);
        #pragma unroll
        for (int q = 0; q < 5; q++) upk2(TCs[2 * q], TCs[2 * q + 1], C1[q]);
        epilogue(TAs, TBs, TCs, W0, W1, W2, W3, W4, W5, e, m1, obase);
    }
}

// ---------------------------------------------------------------------------
extern "C" void kernel_launch(void* const* d_in, const int* in_sizes, int n_in,
                              void* d_out, int out_size)
{
    const float* feats   = (const float*)d_in[0];
    const int*   species = (const int*)  d_in[1];
    const float* b0 = (const float*)d_in[2];
    const float* w0 = (const float*)d_in[3];
    const float* b1 = (const float*)d_in[4];
    const float* w1 = (const float*)d_in[5];
    const float* b2 = (const float*)d_in[6];
    const float* w2 = (const float*)d_in[7];
    const float* b3 = (const float*)d_in[8];
    const float* w3 = (const float*)d_in[9];
    const float* b4 = (const float*)d_in[10];
    const float* w4 = (const float*)d_in[11];
    const float* b5 = (const float*)d_in[12];
    const float* w5 = (const float*)d_in[13];
    float* out = (float*)d_out;

    dim3 block(64, 8);
    dim3 grid(2048 / 8);
    symcon_kernel<<<grid, block>>>(feats, species,
                                   b0, b1, b2, b3, b4, b5,
                                   w0, w1, w2, w3, w4, w5, out);
}